// round 14
// baseline (speedup 1.0000x reference)
#include <cuda_runtime.h>
#include <cuda_fp16.h>
#include <cstdint>

#define NN 512
#define HH 8
#define RDC 4096
#define MRN 65536
#define ASTG_H 9216    // halves per smem stage (128 rows * 144B)
#define SMEM_BYTES 110592

__device__ __align__(16) __half g_xh  [MRN * 128];
__device__ __align__(16) __half g_wt  [896 * 128];
__device__ __align__(16) __half g_woutt[128 * 256];
__device__ __align__(16) __half g_qh  [HH * NN * RDC];
__device__ __align__(16) __half g_kh  [HH * NN * RDC];
__device__ __align__(16) __half g_vh  [HH * NN * RDC];
__device__ __align__(16) __half g_ph  [HH * NN * NN];
__device__ __align__(16) __half g_o2  [MRN * 256];
__device__ __align__(16) float  g_dots[HH * NN * NN];
__device__ __align__(16) float  g_pbh [HH * NN * NN];
__device__ __align__(16) float  g_qsw [NN * 128];
__device__ __align__(16) float  g_wrow[NN * HH * 128];

__device__ __forceinline__ uint32_t smem_u32(const void* p) {
    uint32_t a;
    asm("{ .reg .u64 t; cvta.to.shared.u64 t, %1; cvt.u32.u64 %0, t; }" : "=r"(a) : "l"(p));
    return a;
}
__device__ __forceinline__ void ldm4(uint32_t* r, uint32_t addr) {
    asm volatile("ldmatrix.sync.aligned.m8n8.x4.shared.b16 {%0,%1,%2,%3}, [%4];"
                 : "=r"(r[0]), "=r"(r[1]), "=r"(r[2]), "=r"(r[3]) : "r"(addr));
}
__device__ __forceinline__ void ldm4t(uint32_t* r, uint32_t addr) {
    asm volatile("ldmatrix.sync.aligned.m8n8.x4.trans.shared.b16 {%0,%1,%2,%3}, [%4];"
                 : "=r"(r[0]), "=r"(r[1]), "=r"(r[2]), "=r"(r[3]) : "r"(addr));
}
__device__ __forceinline__ void mma16(float* c, const uint32_t* a, const uint32_t* b) {
    asm volatile("mma.sync.aligned.m16n8k16.row.col.f32.f16.f16.f32 "
        "{%0,%1,%2,%3},{%4,%5,%6,%7},{%8,%9},{%0,%1,%2,%3};"
        : "+f"(c[0]), "+f"(c[1]), "+f"(c[2]), "+f"(c[3])
        : "r"(a[0]), "r"(a[1]), "r"(a[2]), "r"(a[3]), "r"(b[0]), "r"(b[1]));
}
#define CPA16(dst, src) \
    asm volatile("cp.async.cg.shared.global [%0], [%1], 16;" :: "r"(dst), "l"(src) : "memory")

// ============================================================================
// fp16 GEMM: block 128x128, 8 warps (64x32), ktile 64, 3-stage, 1 sync/ktile.
// MODE: 0=qkv, 1=dots, 2=O trans-B, 3=out, 4=ksw (fused sw-reduce)
// ============================================================================
template<int MODE, int KT>
__global__ __launch_bounds__(256) void g16(const float* __restrict__ auxA,
                                           float* __restrict__ outp) {
    extern __shared__ __half sh[];
    __half* AsB = sh;
    __half* BsB = sh + 3 * ASTG_H;
    const int t = threadIdx.x, lane = t & 31, warp = t >> 5;
    const int bx = blockIdx.x, by = blockIdx.y, h = blockIdx.z;

    const __half *A, *B; int lda, ldb;
    if (MODE == 0)      { A = g_xh + (size_t)by * 128 * 128; lda = 128;
                          B = g_wt + (size_t)bx * 128 * 128; ldb = 128; }
    else if (MODE == 4) { A = g_xh + (size_t)by * 128 * 128; lda = 128;
                          B = g_wt + (size_t)768 * 128;      ldb = 128; }
    else if (MODE == 1) { A = g_qh + ((size_t)h * 512 + by * 128) * 4096; lda = 4096;
                          B = g_kh + ((size_t)h * 512 + bx * 128) * 4096; ldb = 4096; }
    else if (MODE == 2) { A = g_ph + ((size_t)h * 512 + by * 128) * 512; lda = 512;
                          B = g_vh + (size_t)h * 512 * 4096 + bx * 128;  ldb = 4096; }
    else                { A = g_o2 + (size_t)by * 128 * 256; lda = 256;
                          B = g_woutt;                       ldb = 256; }

    auto cpst = [&](int st, int k0) {
        uint32_t da = smem_u32(AsB + st * ASTG_H), db = smem_u32(BsB + st * ASTG_H);
#pragma unroll
        for (int c = t; c < 1024; c += 256) {
            int row = c >> 3, col = c & 7;
            CPA16(da + row * 144 + col * 16, A + (size_t)row * lda + k0 + col * 8);
        }
        if (MODE == 2) {
#pragma unroll
            for (int c = t; c < 1024; c += 256) {
                int row = c >> 4, col = c & 15;
                CPA16(db + row * 272 + col * 16, B + (size_t)(k0 + row) * ldb + col * 8);
            }
        } else {
#pragma unroll
            for (int c = t; c < 1024; c += 256) {
                int row = c >> 3, col = c & 7;
                CPA16(db + row * 144 + col * 16, B + (size_t)row * ldb + k0 + col * 8);
            }
        }
        asm volatile("cp.async.commit_group;" ::: "memory");
    };

    float acc[4][4][4] = {};
    const int wm0 = (warp >> 2) * 64, wn0 = (warp & 3) * 32;
    const int q = lane >> 3;

    cpst(0, 0);
    if (KT > 1) cpst(1, 64);
    int st = 0;
    for (int kt = 0; kt < KT; kt++) {
        if (kt + 1 < KT) asm volatile("cp.async.wait_group 1;" ::: "memory");
        else             asm volatile("cp.async.wait_group 0;" ::: "memory");
        __syncthreads();
        uint32_t ab = smem_u32(AsB + st * ASTG_H), bb = smem_u32(BsB + st * ASTG_H);
#pragma unroll
        for (int kk = 0; kk < 64; kk += 16) {
            uint32_t af[4][4], bf[2][4];
#pragma unroll
            for (int mt = 0; mt < 4; mt++)
                ldm4(af[mt], ab + (wm0 + mt * 16 + (lane & 15)) * 144 + (kk + (lane >> 4) * 8) * 2);
#pragma unroll
            for (int np = 0; np < 2; np++) {
                if (MODE == 2)
                    ldm4t(bf[np], bb + (kk + (q & 1) * 8 + (lane & 7)) * 272
                                     + (wn0 + np * 16 + (q >> 1) * 8) * 2);
                else
                    ldm4(bf[np], bb + (wn0 + np * 16 + (q >> 1) * 8 + (lane & 7)) * 144
                                    + (kk + (q & 1) * 8) * 2);
            }
#pragma unroll
            for (int mt = 0; mt < 4; mt++)
#pragma unroll
                for (int nt = 0; nt < 4; nt++)
                    mma16(acc[mt][nt], af[mt], &bf[nt >> 1][(nt & 1) * 2]);
        }
        if (kt + 2 < KT) {
            int ns = st + 2; if (ns >= 3) ns -= 3;
            cpst(ns, (kt + 2) * 64);
        }
        st = (st == 2) ? 0 : st + 1;
    }

    if (MODE == 4) {
#pragma unroll
        for (int mt = 0; mt < 4; mt++)
#pragma unroll
            for (int hf = 0; hf < 2; hf++) {
                int mrow = wm0 + mt * 16 + (lane >> 2) + hf * 8;
                int m = by * 128 + mrow, r = m >> 9, n = m & 511;
                float p[2] = {0.f, 0.f};
#pragma unroll
                for (int nt = 0; nt < 4; nt++) {
                    int c = wn0 + nt * 8 + (lane & 3) * 2;
                    float v0 = acc[mt][nt][hf * 2]     + auxA[c];
                    float v1 = acc[mt][nt][hf * 2 + 1] + auxA[c + 1];
                    p[nt >> 1] += v0 * g_qsw[n * 128 + c] + v1 * g_qsw[n * 128 + c + 1];
                }
#pragma unroll
                for (int hi = 0; hi < 2; hi++) {
                    p[hi] += __shfl_xor_sync(0xffffffffu, p[hi], 1);
                    p[hi] += __shfl_xor_sync(0xffffffffu, p[hi], 2);
                }
                if ((lane & 3) == 0) {
                    int h0 = wn0 >> 4;
                    g_wrow[(n * 8 + h0) * 128 + r]     = p[0] * 0.25f;
                    g_wrow[(n * 8 + h0 + 1) * 128 + r] = p[1] * 0.25f;
                }
            }
        return;
    }

#pragma unroll
    for (int mt = 0; mt < 4; mt++)
#pragma unroll
        for (int nt = 0; nt < 4; nt++)
#pragma unroll
            for (int hf = 0; hf < 2; hf++) {
                int mrow = wm0 + mt * 16 + (lane >> 2) + hf * 8;
                int ncol = wn0 + nt * 8 + (lane & 3) * 2;
                float v0 = acc[mt][nt][hf * 2], v1 = acc[mt][nt][hf * 2 + 1];
                if (MODE == 0) {
                    int m = by * 128 + mrow, c = bx * 128 + ncol;
                    int r = m >> 9, n = m & 511;
                    if (c < 256) {
                        int hh = c >> 5, d = c & 31;
                        float w = g_wrow[(n * 8 + hh) * 128 + r];
                        *reinterpret_cast<__half2*>(
                            &g_qh[((size_t)(hh * 512 + n)) * 4096 + r * 32 + d]) =
                            __floats2half2_rn(v0 * w, v1 * w);
                    } else if (c < 512) {
                        int cc = c - 256, hh = cc >> 5, d = cc & 31;
                        *reinterpret_cast<__half2*>(
                            &g_kh[((size_t)(hh * 512 + n)) * 4096 + r * 32 + d]) =
                            __floats2half2_rn(v0, v1);
                    } else {
                        int cc = c - 512, hh = cc >> 5, d = cc & 31;
                        *reinterpret_cast<__half2*>(
                            &g_vh[((size_t)(hh * 512 + n)) * 4096 + r * 32 + d]) =
                            __floats2half2_rn(v0, v1);
                    }
                } else if (MODE == 1) {
                    int i = by * 128 + mrow, j = bx * 128 + ncol;
                    size_t off = ((size_t)h * 512 + i) * 512 + j;
                    g_dots[off]     = v0;
                    g_dots[off + 1] = v1;
                } else if (MODE == 2) {
                    int i = by * 128 + mrow, tcol = bx * 128 + ncol;
                    int r = tcol >> 5, d = tcol & 31;
                    *reinterpret_cast<__half2*>(
                        &g_o2[((size_t)r * 512 + i) * 256 + h * 32 + d]) =
                        __floats2half2_rn(v0, v1);
                } else {
                    int m = by * 128 + mrow;
                    outp[(size_t)m * 128 + ncol]     = v0 + auxA[ncol];
                    outp[(size_t)m * 128 + ncol + 1] = v1 + auxA[ncol + 1];
                }
            }
}

// ============================================================================
// pbh: warp per 4 consecutive rows (same i, j..j+3); split-tree head reduce;
// writers emit one float4 store per head plane.
// ============================================================================
__global__ __launch_bounds__(256) void pbh_kernel(const float* __restrict__ pair_bias,
                                                  const float* __restrict__ ln_g,
                                                  const float* __restrict__ ln_b,
                                                  const float* __restrict__ Wpair) {
    const int lane = threadIdx.x & 31;
    const int gw = (blockIdx.x * 256 + threadIdx.x) >> 5;
    const int nw = (gridDim.x * 256) >> 5;
    const int p0 = lane * 4;

    float gg[4], bb4[4], wp[4][8];
#pragma unroll
    for (int e = 0; e < 4; e++) {
        gg[e]  = ln_g[p0 + e];
        bb4[e] = ln_b[p0 + e];
        float4 w0 = *reinterpret_cast<const float4*>(&Wpair[(p0 + e) * 8]);
        float4 w1 = *reinterpret_cast<const float4*>(&Wpair[(p0 + e) * 8 + 4]);
        wp[e][0] = w0.x; wp[e][1] = w0.y; wp[e][2] = w0.z; wp[e][3] = w0.w;
        wp[e][4] = w1.x; wp[e][5] = w1.y; wp[e][6] = w1.z; wp[e][7] = w1.w;
    }
    const int myh = ((lane >> 4) & 1) * 4 + ((lane >> 3) & 1) * 2 + ((lane >> 2) & 1);
    const bool writer = (lane & 3) == 0;

    for (int idx = gw * 4; idx < NN * NN; idx += nw * 4) {
        float vv[4][4];
        float s[4], sq[4];
#pragma unroll
        for (int rr = 0; rr < 4; rr++) {
            float4 v = *reinterpret_cast<const float4*>(&pair_bias[(size_t)(idx + rr) * 128 + p0]);
            vv[rr][0] = v.x; vv[rr][1] = v.y; vv[rr][2] = v.z; vv[rr][3] = v.w;
            s[rr]  = v.x + v.y + v.z + v.w;
            sq[rr] = v.x * v.x + v.y * v.y + v.z * v.z + v.w * v.w;
        }
#pragma unroll
        for (int o = 16; o; o >>= 1) {
#pragma unroll
            for (int rr = 0; rr < 4; rr++) {
                s[rr]  += __shfl_xor_sync(0xffffffffu, s[rr], o);
                sq[rr] += __shfl_xor_sync(0xffffffffu, sq[rr], o);
            }
        }
        float res[4];
#pragma unroll
        for (int rr = 0; rr < 4; rr++) {
            float mean = s[rr] * (1.0f / 128.0f);
            float var  = sq[rr] * (1.0f / 128.0f) - mean * mean;
            float rstd = rsqrtf(var + 1e-5f);
            float v[8] = {};
#pragma unroll
            for (int e = 0; e < 4; e++) {
                float nz = (vv[rr][e] - mean) * rstd * gg[e] + bb4[e];
#pragma unroll
                for (int hh = 0; hh < 8; hh++) v[hh] += nz * wp[e][hh];
            }
            // split-tree: 8 -> 4 -> 2 -> 1 live values
#pragma unroll
            for (int hh = 0; hh < 8; hh++) v[hh] += __shfl_xor_sync(0xffffffffu, v[hh], 16);
            if (lane & 16) { v[0] = v[4]; v[1] = v[5]; v[2] = v[6]; v[3] = v[7]; }
#pragma unroll
            for (int hh = 0; hh < 4; hh++) v[hh] += __shfl_xor_sync(0xffffffffu, v[hh], 8);
            if (lane & 8) { v[0] = v[2]; v[1] = v[3]; }
#pragma unroll
            for (int hh = 0; hh < 2; hh++) v[hh] += __shfl_xor_sync(0xffffffffu, v[hh], 4);
            if (lane & 4) { v[0] = v[1]; }
            v[0] += __shfl_xor_sync(0xffffffffu, v[0], 2);
            v[0] += __shfl_xor_sync(0xffffffffu, v[0], 1);
            res[rr] = v[0];
        }
        if (writer) {
            int i = idx >> 9, j0 = idx & 511;
            float4 o4 = make_float4(res[0], res[1], res[2], res[3]);
            *reinterpret_cast<float4*>(&g_pbh[(((size_t)myh << 9) + i) * NN + j0]) = o4;
        }
    }
}

// ============================================================================
__global__ void conv_x(const float* __restrict__ x) {
    size_t i = ((size_t)blockIdx.x * 256 + threadIdx.x) * 4;
    float4 v = *reinterpret_cast<const float4*>(x + i);
    __half2* d = reinterpret_cast<__half2*>(&g_xh[i]);
    d[0] = __floats2half2_rn(v.x, v.y);
    d[1] = __floats2half2_rn(v.z, v.w);
}

__global__ void conv_w(const float* __restrict__ Wq, const float* __restrict__ Wkv,
                       const float* __restrict__ Wk_sw, const float* __restrict__ Wout) {
    int g = blockIdx.x * 256 + threadIdx.x;
    if (g < 114688) {
        int row = g >> 7, k = g & 127;
        float v;
        if (row < 256)      v = Wq[k * 256 + row];
        else if (row < 768) v = Wkv[k * 512 + (row - 256)];
        else                v = Wk_sw[k * 128 + (row - 768)];
        g_wt[g] = __float2half_rn(v);
    } else {
        int g2 = g - 114688;
        int c = g2 >> 8, k = g2 & 255;
        g_woutt[g2] = __float2half_rn(Wout[k * 128 + c]);
    }
}

__global__ void qsw_kernel(const float* __restrict__ x, const float* __restrict__ Wq_sw,
                           const float* __restrict__ bq_sw) {
    int n = blockIdx.x, c = threadIdx.x;
    __shared__ float xr[128];
    xr[c] = x[(size_t)n * 128 + c];
    __syncthreads();
    float acc = bq_sw[c];
#pragma unroll 8
    for (int k = 0; k < 128; k++) acc += xr[k] * Wq_sw[k * 128 + c];
    g_qsw[n * 128 + c] = acc;
}

__global__ void wrow_softmax_kernel() {
    int row = blockIdx.x, t = threadIdx.x;
    float v = g_wrow[(size_t)row * 128 + t];
    __shared__ float sm[128];
    sm[t] = v; __syncthreads();
#pragma unroll
    for (int s = 64; s > 0; s >>= 1) { if (t < s) sm[t] = fmaxf(sm[t], sm[t + s]); __syncthreads(); }
    float mx = sm[0]; __syncthreads();
    float e = expf(v - mx);
    sm[t] = e; __syncthreads();
#pragma unroll
    for (int s = 64; s > 0; s >>= 1) { if (t < s) sm[t] += sm[t + s]; __syncthreads(); }
    g_wrow[(size_t)row * 128 + t] = e / sm[0];
}

__global__ void attn_softmax_kernel() {
    size_t row = blockIdx.x;
    int t = threadIdx.x;
    size_t off0 = row * 512 + t, off1 = off0 + 256;
    const float scale = 0.17677669529663687f;
    float v0 = g_dots[off0] * scale + g_pbh[off0];
    float v1 = g_dots[off1] * scale + g_pbh[off1];
    __shared__ float sm[256];
    sm[t] = fmaxf(v0, v1); __syncthreads();
#pragma unroll
    for (int s = 128; s > 0; s >>= 1) { if (t < s) sm[t] = fmaxf(sm[t], sm[t + s]); __syncthreads(); }
    float mx = sm[0]; __syncthreads();
    float e0 = expf(v0 - mx), e1 = expf(v1 - mx);
    sm[t] = e0 + e1; __syncthreads();
#pragma unroll
    for (int s = 128; s > 0; s >>= 1) { if (t < s) sm[t] += sm[t + s]; __syncthreads(); }
    float inv = 1.0f / sm[0];
    g_ph[row * 512 + t]       = __float2half_rn(e0 * inv);
    g_ph[row * 512 + t + 256] = __float2half_rn(e1 * inv);
}

// ============================================================================
extern "C" void kernel_launch(void* const* d_in, const int* in_sizes, int n_in,
                              void* d_out, int out_size) {
    (void)in_sizes; (void)n_in; (void)out_size;
    const float* x         = (const float*)d_in[0];
    const float* pair_bias = (const float*)d_in[1];
    const float* Wq        = (const float*)d_in[2];
    const float* Wkv       = (const float*)d_in[3];
    const float* Wout      = (const float*)d_in[4];
    const float* b_out     = (const float*)d_in[5];
    const float* ln_g      = (const float*)d_in[6];
    const float* ln_b      = (const float*)d_in[7];
    const float* Wpair     = (const float*)d_in[8];
    const float* Wq_sw     = (const float*)d_in[9];
    const float* bq_sw     = (const float*)d_in[10];
    const float* Wk_sw     = (const float*)d_in[11];
    const float* bk_sw     = (const float*)d_in[12];
    float* out = (float*)d_out;

    static int attr_done = 0;
    if (!attr_done) {
        cudaFuncSetAttribute(g16<0, 2>,  cudaFuncAttributeMaxDynamicSharedMemorySize, SMEM_BYTES);
        cudaFuncSetAttribute(g16<1, 64>, cudaFuncAttributeMaxDynamicSharedMemorySize, SMEM_BYTES);
        cudaFuncSetAttribute(g16<2, 8>,  cudaFuncAttributeMaxDynamicSharedMemorySize, SMEM_BYTES);
        cudaFuncSetAttribute(g16<3, 4>,  cudaFuncAttributeMaxDynamicSharedMemorySize, SMEM_BYTES);
        cudaFuncSetAttribute(g16<4, 2>,  cudaFuncAttributeMaxDynamicSharedMemorySize, SMEM_BYTES);
        attr_done = 1;
    }

    conv_x             <<<8192, 256>>>(x);
    conv_w             <<<576, 256>>>(Wq, Wkv, Wk_sw, Wout);
    qsw_kernel         <<<NN, 128>>>(x, Wq_sw, bq_sw);
    g16<4, 2>          <<<dim3(1, 512), 256, SMEM_BYTES>>>(bk_sw, nullptr);  // ksw: profiled slot
    pbh_kernel         <<<2048, 256>>>(pair_bias, ln_g, ln_b, Wpair);
    wrow_softmax_kernel<<<NN * HH, 128>>>();
    g16<0, 2>          <<<dim3(6, 512), 256, SMEM_BYTES>>>(nullptr, nullptr);  // qkv
    g16<1, 64>         <<<dim3(4, 4, 8), 256, SMEM_BYTES>>>(nullptr, nullptr); // dots sK=1
    attn_softmax_kernel<<<HH * NN, 256>>>();
    g16<2, 8>          <<<dim3(32, 4, 8), 256, SMEM_BYTES>>>(nullptr, nullptr); // O
    g16<3, 4>          <<<dim3(1, 512), 256, SMEM_BYTES>>>(b_out, out);         // out
}

// round 15
// speedup vs baseline: 1.0349x; 1.0349x over previous
#include <cuda_runtime.h>
#include <cuda_fp16.h>
#include <cstdint>

#define NN 512
#define HH 8
#define RDC 4096
#define MRN 65536
#define DPL 2097152    // one dots plane
#define ASTG_H 9216    // halves per smem stage (128 rows * 144B)
#define SMEM_BYTES 110592
#define SMEM_QKV 92160 // (2 A + 3 B) stages

__device__ __align__(16) __half g_xh  [MRN * 128];
__device__ __align__(16) __half g_wt  [896 * 128];
__device__ __align__(16) __half g_woutt[128 * 256];
__device__ __align__(16) __half g_qh  [HH * NN * RDC];
__device__ __align__(16) __half g_kh  [HH * NN * RDC];
__device__ __align__(16) __half g_vh  [HH * NN * RDC];
__device__ __align__(16) __half g_ph  [HH * NN * NN];
__device__ __align__(16) __half g_o2  [MRN * 256];
__device__ __align__(16) float  g_dots[2 * DPL];
__device__ __align__(16) float  g_pbh [HH * NN * NN];
__device__ __align__(16) float  g_qsw [NN * 128];
__device__ __align__(16) float  g_wrow[NN * HH * 128];

__device__ __forceinline__ uint32_t smem_u32(const void* p) {
    uint32_t a;
    asm("{ .reg .u64 t; cvta.to.shared.u64 t, %1; cvt.u32.u64 %0, t; }" : "=r"(a) : "l"(p));
    return a;
}
__device__ __forceinline__ void ldm4(uint32_t* r, uint32_t addr) {
    asm volatile("ldmatrix.sync.aligned.m8n8.x4.shared.b16 {%0,%1,%2,%3}, [%4];"
                 : "=r"(r[0]), "=r"(r[1]), "=r"(r[2]), "=r"(r[3]) : "r"(addr));
}
__device__ __forceinline__ void ldm4t(uint32_t* r, uint32_t addr) {
    asm volatile("ldmatrix.sync.aligned.m8n8.x4.trans.shared.b16 {%0,%1,%2,%3}, [%4];"
                 : "=r"(r[0]), "=r"(r[1]), "=r"(r[2]), "=r"(r[3]) : "r"(addr));
}
__device__ __forceinline__ void mma16(float* c, const uint32_t* a, const uint32_t* b) {
    asm volatile("mma.sync.aligned.m16n8k16.row.col.f32.f16.f16.f32 "
        "{%0,%1,%2,%3},{%4,%5,%6,%7},{%8,%9},{%0,%1,%2,%3};"
        : "+f"(c[0]), "+f"(c[1]), "+f"(c[2]), "+f"(c[3])
        : "r"(a[0]), "r"(a[1]), "r"(a[2]), "r"(a[3]), "r"(b[0]), "r"(b[1]));
}
#define CPA16(dst, src) \
    asm volatile("cp.async.cg.shared.global [%0], [%1], 16;" :: "r"(dst), "l"(src) : "memory")

// ============================================================================
// generic fp16 GEMM: block 128x128, 8 warps (64x32), ktile 64, 3-stage.
// MODE: 1=dots(split-K=2), 2=O trans-B, 3=out, 4=ksw (fused sw-reduce)
// ============================================================================
template<int MODE, int KT>
__global__ __launch_bounds__(256) void g16(const float* __restrict__ auxA,
                                           float* __restrict__ outp) {
    extern __shared__ __half sh[];
    __half* AsB = sh;
    __half* BsB = sh + 3 * ASTG_H;
    const int t = threadIdx.x, lane = t & 31, warp = t >> 5;
    const int bx = blockIdx.x, by = blockIdx.y;
    const int h = (MODE == 1) ? (blockIdx.z & 7) : blockIdx.z;
    const int split = (MODE == 1) ? (blockIdx.z >> 3) : 0;

    const __half *A, *B; int lda, ldb;
    if (MODE == 4)      { A = g_xh + (size_t)by * 128 * 128; lda = 128;
                          B = g_wt + (size_t)768 * 128;      ldb = 128; }
    else if (MODE == 1) { A = g_qh + ((size_t)h * 512 + by * 128) * 4096 + split * 2048; lda = 4096;
                          B = g_kh + ((size_t)h * 512 + bx * 128) * 4096 + split * 2048; ldb = 4096; }
    else if (MODE == 2) { A = g_ph + ((size_t)h * 512 + by * 128) * 512; lda = 512;
                          B = g_vh + (size_t)h * 512 * 4096 + bx * 128;  ldb = 4096; }
    else                { A = g_o2 + (size_t)by * 128 * 256; lda = 256;
                          B = g_woutt;                       ldb = 256; }

    auto cpst = [&](int st, int k0) {
        uint32_t da = smem_u32(AsB + st * ASTG_H), db = smem_u32(BsB + st * ASTG_H);
#pragma unroll
        for (int c = t; c < 1024; c += 256) {
            int row = c >> 3, col = c & 7;
            CPA16(da + row * 144 + col * 16, A + (size_t)row * lda + k0 + col * 8);
        }
        if (MODE == 2) {
#pragma unroll
            for (int c = t; c < 1024; c += 256) {
                int row = c >> 4, col = c & 15;
                CPA16(db + row * 272 + col * 16, B + (size_t)(k0 + row) * ldb + col * 8);
            }
        } else {
#pragma unroll
            for (int c = t; c < 1024; c += 256) {
                int row = c >> 3, col = c & 7;
                CPA16(db + row * 144 + col * 16, B + (size_t)row * ldb + k0 + col * 8);
            }
        }
        asm volatile("cp.async.commit_group;" ::: "memory");
    };

    float acc[4][4][4] = {};
    const int wm0 = (warp >> 2) * 64, wn0 = (warp & 3) * 32;
    const int q = lane >> 3;

    cpst(0, 0);
    if (KT > 1) cpst(1, 64);
    int st = 0;
    for (int kt = 0; kt < KT; kt++) {
        if (kt + 1 < KT) asm volatile("cp.async.wait_group 1;" ::: "memory");
        else             asm volatile("cp.async.wait_group 0;" ::: "memory");
        __syncthreads();
        uint32_t ab = smem_u32(AsB + st * ASTG_H), bb = smem_u32(BsB + st * ASTG_H);
#pragma unroll
        for (int kk = 0; kk < 64; kk += 16) {
            uint32_t af[4][4], bf[2][4];
#pragma unroll
            for (int mt = 0; mt < 4; mt++)
                ldm4(af[mt], ab + (wm0 + mt * 16 + (lane & 15)) * 144 + (kk + (lane >> 4) * 8) * 2);
#pragma unroll
            for (int np = 0; np < 2; np++) {
                if (MODE == 2)
                    ldm4t(bf[np], bb + (kk + (q & 1) * 8 + (lane & 7)) * 272
                                     + (wn0 + np * 16 + (q >> 1) * 8) * 2);
                else
                    ldm4(bf[np], bb + (wn0 + np * 16 + (q >> 1) * 8 + (lane & 7)) * 144
                                    + (kk + (q & 1) * 8) * 2);
            }
#pragma unroll
            for (int mt = 0; mt < 4; mt++)
#pragma unroll
                for (int nt = 0; nt < 4; nt++)
                    mma16(acc[mt][nt], af[mt], &bf[nt >> 1][(nt & 1) * 2]);
        }
        if (kt + 2 < KT) {
            int ns = st + 2; if (ns >= 3) ns -= 3;
            cpst(ns, (kt + 2) * 64);
        }
        st = (st == 2) ? 0 : st + 1;
    }

    if (MODE == 4) {
#pragma unroll
        for (int mt = 0; mt < 4; mt++)
#pragma unroll
            for (int hf = 0; hf < 2; hf++) {
                int mrow = wm0 + mt * 16 + (lane >> 2) + hf * 8;
                int m = by * 128 + mrow, r = m >> 9, n = m & 511;
                float p[2] = {0.f, 0.f};
#pragma unroll
                for (int nt = 0; nt < 4; nt++) {
                    int c = wn0 + nt * 8 + (lane & 3) * 2;
                    float v0 = acc[mt][nt][hf * 2]     + auxA[c];
                    float v1 = acc[mt][nt][hf * 2 + 1] + auxA[c + 1];
                    p[nt >> 1] += v0 * g_qsw[n * 128 + c] + v1 * g_qsw[n * 128 + c + 1];
                }
#pragma unroll
                for (int hi = 0; hi < 2; hi++) {
                    p[hi] += __shfl_xor_sync(0xffffffffu, p[hi], 1);
                    p[hi] += __shfl_xor_sync(0xffffffffu, p[hi], 2);
                }
                if ((lane & 3) == 0) {
                    int h0 = wn0 >> 4;
                    g_wrow[(n * 8 + h0) * 128 + r]     = p[0] * 0.25f;
                    g_wrow[(n * 8 + h0 + 1) * 128 + r] = p[1] * 0.25f;
                }
            }
        return;
    }

#pragma unroll
    for (int mt = 0; mt < 4; mt++)
#pragma unroll
        for (int nt = 0; nt < 4; nt++)
#pragma unroll
            for (int hf = 0; hf < 2; hf++) {
                int mrow = wm0 + mt * 16 + (lane >> 2) + hf * 8;
                int ncol = wn0 + nt * 8 + (lane & 3) * 2;
                float v0 = acc[mt][nt][hf * 2], v1 = acc[mt][nt][hf * 2 + 1];
                if (MODE == 1) {
                    int i = by * 128 + mrow, j = bx * 128 + ncol;
                    size_t off = (size_t)split * DPL + ((size_t)h * 512 + i) * 512 + j;
                    g_dots[off]     = v0;
                    g_dots[off + 1] = v1;
                } else if (MODE == 2) {
                    int i = by * 128 + mrow, tcol = bx * 128 + ncol;
                    int r = tcol >> 5, d = tcol & 31;
                    *reinterpret_cast<__half2*>(
                        &g_o2[((size_t)r * 512 + i) * 256 + h * 32 + d]) =
                        __floats2half2_rn(v0, v1);
                } else {
                    int m = by * 128 + mrow;
                    outp[(size_t)m * 128 + ncol]     = v0 + auxA[ncol];
                    outp[(size_t)m * 128 + ncol + 1] = v1 + auxA[ncol + 1];
                }
            }
}

// ============================================================================
// qkv: one CTA per 128-row block; A (128x128) staged ONCE; loop over 6 weight
// tiles with 3-stage B pipeline.  Epilogue scatters q(*w_row)/k/v.
// ============================================================================
__global__ __launch_bounds__(256) void qkv6() {
    extern __shared__ __half sh[];
    __half* AsB = sh;                 // 2 ktile tiles of A
    __half* BsB = sh + 2 * ASTG_H;    // 3 B stages
    const int t = threadIdx.x, lane = t & 31, warp = t >> 5;
    const int by = blockIdx.y;
    const __half* A = g_xh + (size_t)by * 128 * 128;

    // stage all of A (two 64-k tiles)
#pragma unroll
    for (int kt = 0; kt < 2; kt++) {
        uint32_t da = smem_u32(AsB + kt * ASTG_H);
#pragma unroll
        for (int c = t; c < 1024; c += 256) {
            int row = c >> 3, col = c & 7;
            CPA16(da + row * 144 + col * 16, A + (size_t)row * 128 + kt * 64 + col * 8);
        }
    }
    asm volatile("cp.async.commit_group;" ::: "memory");

    auto cpB = [&](int st, int it) {     // it = cb*2 + kt
        const __half* B = g_wt + (size_t)(it >> 1) * 128 * 128 + (it & 1) * 64;
        uint32_t db = smem_u32(BsB + st * ASTG_H);
#pragma unroll
        for (int c = t; c < 1024; c += 256) {
            int row = c >> 3, col = c & 7;
            CPA16(db + row * 144 + col * 16, B + (size_t)row * 128 + col * 8);
        }
        asm volatile("cp.async.commit_group;" ::: "memory");
    };

    cpB(0, 0);
    cpB(1, 1);
    float acc[4][4][4] = {};
    const int wm0 = (warp >> 2) * 64, wn0 = (warp & 3) * 32;
    const int q = lane >> 3;

    int st = 0;
    for (int it = 0; it < 12; it++) {
        if (it + 1 < 12) asm volatile("cp.async.wait_group 1;" ::: "memory");
        else             asm volatile("cp.async.wait_group 0;" ::: "memory");
        __syncthreads();
        if (it + 2 < 12) {
            int ns = st + 2; if (ns >= 3) ns -= 3;
            cpB(ns, it + 2);
        }
        uint32_t ab = smem_u32(AsB + (it & 1) * ASTG_H), bb = smem_u32(BsB + st * ASTG_H);
#pragma unroll
        for (int kk = 0; kk < 64; kk += 16) {
            uint32_t af[4][4], bf[2][4];
#pragma unroll
            for (int mt = 0; mt < 4; mt++)
                ldm4(af[mt], ab + (wm0 + mt * 16 + (lane & 15)) * 144 + (kk + (lane >> 4) * 8) * 2);
#pragma unroll
            for (int np = 0; np < 2; np++)
                ldm4(bf[np], bb + (wn0 + np * 16 + (q >> 1) * 8 + (lane & 7)) * 144
                                + (kk + (q & 1) * 8) * 2);
#pragma unroll
            for (int mt = 0; mt < 4; mt++)
#pragma unroll
                for (int nt = 0; nt < 4; nt++)
                    mma16(acc[mt][nt], af[mt], &bf[nt >> 1][(nt & 1) * 2]);
        }
        st = (st == 2) ? 0 : st + 1;

        if (it & 1) {
            const int cb = it >> 1;
#pragma unroll
            for (int mt = 0; mt < 4; mt++)
#pragma unroll
                for (int nt = 0; nt < 4; nt++)
#pragma unroll
                    for (int hf = 0; hf < 2; hf++) {
                        int mrow = wm0 + mt * 16 + (lane >> 2) + hf * 8;
                        int ncol = wn0 + nt * 8 + (lane & 3) * 2;
                        int m = by * 128 + mrow, c = cb * 128 + ncol;
                        int r = m >> 9, n = m & 511;
                        float v0 = acc[mt][nt][hf * 2], v1 = acc[mt][nt][hf * 2 + 1];
                        if (c < 256) {
                            int hh = c >> 5, d = c & 31;
                            float w = g_wrow[(n * 8 + hh) * 128 + r];
                            *reinterpret_cast<__half2*>(
                                &g_qh[((size_t)(hh * 512 + n)) * 4096 + r * 32 + d]) =
                                __floats2half2_rn(v0 * w, v1 * w);
                        } else if (c < 512) {
                            int cc = c - 256, hh = cc >> 5, d = cc & 31;
                            *reinterpret_cast<__half2*>(
                                &g_kh[((size_t)(hh * 512 + n)) * 4096 + r * 32 + d]) =
                                __floats2half2_rn(v0, v1);
                        } else {
                            int cc = c - 512, hh = cc >> 5, d = cc & 31;
                            *reinterpret_cast<__half2*>(
                                &g_vh[((size_t)(hh * 512 + n)) * 4096 + r * 32 + d]) =
                                __floats2half2_rn(v0, v1);
                        }
                        acc[mt][nt][hf * 2] = 0.f;
                        acc[mt][nt][hf * 2 + 1] = 0.f;
                    }
        }
    }
}

// ============================================================================
// pbh: warp per 4 consecutive rows; split-tree head reduce; float4 stores.
// ============================================================================
__global__ __launch_bounds__(256) void pbh_kernel(const float* __restrict__ pair_bias,
                                                  const float* __restrict__ ln_g,
                                                  const float* __restrict__ ln_b,
                                                  const float* __restrict__ Wpair) {
    const int lane = threadIdx.x & 31;
    const int gw = (blockIdx.x * 256 + threadIdx.x) >> 5;
    const int nw = (gridDim.x * 256) >> 5;
    const int p0 = lane * 4;

    float gg[4], bb4[4], wp[4][8];
#pragma unroll
    for (int e = 0; e < 4; e++) {
        gg[e]  = ln_g[p0 + e];
        bb4[e] = ln_b[p0 + e];
        float4 w0 = *reinterpret_cast<const float4*>(&Wpair[(p0 + e) * 8]);
        float4 w1 = *reinterpret_cast<const float4*>(&Wpair[(p0 + e) * 8 + 4]);
        wp[e][0] = w0.x; wp[e][1] = w0.y; wp[e][2] = w0.z; wp[e][3] = w0.w;
        wp[e][4] = w1.x; wp[e][5] = w1.y; wp[e][6] = w1.z; wp[e][7] = w1.w;
    }
    const int myh = ((lane >> 4) & 1) * 4 + ((lane >> 3) & 1) * 2 + ((lane >> 2) & 1);
    const bool writer = (lane & 3) == 0;

    for (int idx = gw * 4; idx < NN * NN; idx += nw * 4) {
        float vv[4][4];
        float s[4], sq[4];
#pragma unroll
        for (int rr = 0; rr < 4; rr++) {
            float4 v = *reinterpret_cast<const float4*>(&pair_bias[(size_t)(idx + rr) * 128 + p0]);
            vv[rr][0] = v.x; vv[rr][1] = v.y; vv[rr][2] = v.z; vv[rr][3] = v.w;
            s[rr]  = v.x + v.y + v.z + v.w;
            sq[rr] = v.x * v.x + v.y * v.y + v.z * v.z + v.w * v.w;
        }
#pragma unroll
        for (int o = 16; o; o >>= 1) {
#pragma unroll
            for (int rr = 0; rr < 4; rr++) {
                s[rr]  += __shfl_xor_sync(0xffffffffu, s[rr], o);
                sq[rr] += __shfl_xor_sync(0xffffffffu, sq[rr], o);
            }
        }
        float res[4];
#pragma unroll
        for (int rr = 0; rr < 4; rr++) {
            float mean = s[rr] * (1.0f / 128.0f);
            float var  = sq[rr] * (1.0f / 128.0f) - mean * mean;
            float rstd = rsqrtf(var + 1e-5f);
            float v[8] = {};
#pragma unroll
            for (int e = 0; e < 4; e++) {
                float nz = (vv[rr][e] - mean) * rstd * gg[e] + bb4[e];
#pragma unroll
                for (int hh = 0; hh < 8; hh++) v[hh] += nz * wp[e][hh];
            }
#pragma unroll
            for (int hh = 0; hh < 8; hh++) v[hh] += __shfl_xor_sync(0xffffffffu, v[hh], 16);
            if (lane & 16) { v[0] = v[4]; v[1] = v[5]; v[2] = v[6]; v[3] = v[7]; }
#pragma unroll
            for (int hh = 0; hh < 4; hh++) v[hh] += __shfl_xor_sync(0xffffffffu, v[hh], 8);
            if (lane & 8) { v[0] = v[2]; v[1] = v[3]; }
#pragma unroll
            for (int hh = 0; hh < 2; hh++) v[hh] += __shfl_xor_sync(0xffffffffu, v[hh], 4);
            if (lane & 4) { v[0] = v[1]; }
            v[0] += __shfl_xor_sync(0xffffffffu, v[0], 2);
            v[0] += __shfl_xor_sync(0xffffffffu, v[0], 1);
            res[rr] = v[0];
        }
        if (writer) {
            int i = idx >> 9, j0 = idx & 511;
            *reinterpret_cast<float4*>(&g_pbh[(((size_t)myh << 9) + i) * NN + j0]) =
                make_float4(res[0], res[1], res[2], res[3]);
        }
    }
}

// ============================================================================
__global__ void conv_x(const float* __restrict__ x) {
    size_t i = ((size_t)blockIdx.x * 256 + threadIdx.x) * 4;
    float4 v = *reinterpret_cast<const float4*>(x + i);
    __half2* d = reinterpret_cast<__half2*>(&g_xh[i]);
    d[0] = __floats2half2_rn(v.x, v.y);
    d[1] = __floats2half2_rn(v.z, v.w);
}

__global__ void conv_w(const float* __restrict__ Wq, const float* __restrict__ Wkv,
                       const float* __restrict__ Wk_sw, const float* __restrict__ Wout) {
    int g = blockIdx.x * 256 + threadIdx.x;
    if (g < 114688) {
        int row = g >> 7, k = g & 127;
        float v;
        if (row < 256)      v = Wq[k * 256 + row];
        else if (row < 768) v = Wkv[k * 512 + (row - 256)];
        else                v = Wk_sw[k * 128 + (row - 768)];
        g_wt[g] = __float2half_rn(v);
    } else {
        int g2 = g - 114688;
        int c = g2 >> 8, k = g2 & 255;
        g_woutt[g2] = __float2half_rn(Wout[k * 128 + c]);
    }
}

__global__ void qsw_kernel(const float* __restrict__ x, const float* __restrict__ Wq_sw,
                           const float* __restrict__ bq_sw) {
    int n = blockIdx.x, c = threadIdx.x;
    __shared__ float xr[128];
    xr[c] = x[(size_t)n * 128 + c];
    __syncthreads();
    float acc = bq_sw[c];
#pragma unroll 8
    for (int k = 0; k < 128; k++) acc += xr[k] * Wq_sw[k * 128 + c];
    g_qsw[n * 128 + c] = acc;
}

__global__ void wrow_softmax_kernel() {
    int row = blockIdx.x, t = threadIdx.x;
    float v = g_wrow[(size_t)row * 128 + t];
    __shared__ float sm[128];
    sm[t] = v; __syncthreads();
#pragma unroll
    for (int s = 64; s > 0; s >>= 1) { if (t < s) sm[t] = fmaxf(sm[t], sm[t + s]); __syncthreads(); }
    float mx = sm[0]; __syncthreads();
    float e = expf(v - mx);
    sm[t] = e; __syncthreads();
#pragma unroll
    for (int s = 64; s > 0; s >>= 1) { if (t < s) sm[t] += sm[t + s]; __syncthreads(); }
    g_wrow[(size_t)row * 128 + t] = e / sm[0];
}

__global__ void attn_softmax_kernel() {
    size_t row = blockIdx.x;
    int t = threadIdx.x;
    size_t off0 = row * 512 + t, off1 = off0 + 256;
    const float scale = 0.17677669529663687f;
    float v0 = (g_dots[off0] + g_dots[off0 + DPL]) * scale + g_pbh[off0];
    float v1 = (g_dots[off1] + g_dots[off1 + DPL]) * scale + g_pbh[off1];
    __shared__ float sm[256];
    sm[t] = fmaxf(v0, v1); __syncthreads();
#pragma unroll
    for (int s = 128; s > 0; s >>= 1) { if (t < s) sm[t] = fmaxf(sm[t], sm[t + s]); __syncthreads(); }
    float mx = sm[0]; __syncthreads();
    float e0 = expf(v0 - mx), e1 = expf(v1 - mx);
    sm[t] = e0 + e1; __syncthreads();
#pragma unroll
    for (int s = 128; s > 0; s >>= 1) { if (t < s) sm[t] += sm[t + s]; __syncthreads(); }
    float inv = 1.0f / sm[0];
    g_ph[row * 512 + t]       = __float2half_rn(e0 * inv);
    g_ph[row * 512 + t + 256] = __float2half_rn(e1 * inv);
}

// ============================================================================
extern "C" void kernel_launch(void* const* d_in, const int* in_sizes, int n_in,
                              void* d_out, int out_size) {
    (void)in_sizes; (void)n_in; (void)out_size;
    const float* x         = (const float*)d_in[0];
    const float* pair_bias = (const float*)d_in[1];
    const float* Wq        = (const float*)d_in[2];
    const float* Wkv       = (const float*)d_in[3];
    const float* Wout      = (const float*)d_in[4];
    const float* b_out     = (const float*)d_in[5];
    const float* ln_g      = (const float*)d_in[6];
    const float* ln_b      = (const float*)d_in[7];
    const float* Wpair     = (const float*)d_in[8];
    const float* Wq_sw     = (const float*)d_in[9];
    const float* bq_sw     = (const float*)d_in[10];
    const float* Wk_sw     = (const float*)d_in[11];
    const float* bk_sw     = (const float*)d_in[12];
    float* out = (float*)d_out;

    static int attr_done = 0;
    if (!attr_done) {
        cudaFuncSetAttribute(qkv6,       cudaFuncAttributeMaxDynamicSharedMemorySize, SMEM_QKV);
        cudaFuncSetAttribute(g16<1, 32>, cudaFuncAttributeMaxDynamicSharedMemorySize, SMEM_BYTES);
        cudaFuncSetAttribute(g16<2, 8>,  cudaFuncAttributeMaxDynamicSharedMemorySize, SMEM_BYTES);
        cudaFuncSetAttribute(g16<3, 4>,  cudaFuncAttributeMaxDynamicSharedMemorySize, SMEM_BYTES);
        cudaFuncSetAttribute(g16<4, 2>,  cudaFuncAttributeMaxDynamicSharedMemorySize, SMEM_BYTES);
        attr_done = 1;
    }

    conv_x             <<<8192, 256>>>(x);
    conv_w             <<<576, 256>>>(Wq, Wkv, Wk_sw, Wout);
    qsw_kernel         <<<NN, 128>>>(x, Wq_sw, bq_sw);
    pbh_kernel         <<<2048, 256>>>(pair_bias, ln_g, ln_b, Wpair);        // 4th: profiled
    g16<4, 2>          <<<dim3(1, 512), 256, SMEM_BYTES>>>(bk_sw, nullptr);  // ksw + fused reduce
    wrow_softmax_kernel<<<NN * HH, 128>>>();
    qkv6               <<<dim3(1, 512), 256, SMEM_QKV>>>();                  // qkv, A staged once
    g16<1, 32>         <<<dim3(4, 4, 16), 256, SMEM_BYTES>>>(nullptr, nullptr); // dots sK=2
    attn_softmax_kernel<<<HH * NN, 256>>>();
    g16<2, 8>          <<<dim3(32, 4, 8), 256, SMEM_BYTES>>>(nullptr, nullptr); // O
    g16<3, 4>          <<<dim3(1, 512), 256, SMEM_BYTES>>>(b_out, out);         // out
}

// round 16
// speedup vs baseline: 1.0513x; 1.0158x over previous
#include <cuda_runtime.h>
#include <cuda_fp16.h>
#include <cstdint>

#define NN 512
#define HH 8
#define RDC 4096
#define MRN 65536
#define DPL 2097152    // one dots plane
#define ASTG_H 9216    // halves per smem stage (128 rows * 144B)
#define SMEM_BYTES 110592
#define SMEM_QKV 92160 // (2 A + 3 B) stages

__device__ __align__(16) __half g_xh  [MRN * 128];
__device__ __align__(16) __half g_wt  [896 * 128];
__device__ __align__(16) __half g_woutt[128 * 256];
__device__ __align__(16) __half g_qh  [HH * NN * RDC];
__device__ __align__(16) __half g_kh  [HH * NN * RDC];
__device__ __align__(16) __half g_vh  [HH * NN * RDC];
__device__ __align__(16) __half g_ph  [HH * NN * NN];
__device__ __align__(16) __half g_o2  [MRN * 256];
__device__ __align__(16) float  g_dots[2 * DPL];
__device__ __align__(16) float  g_pbh [HH * NN * NN];
__device__ __align__(16) float  g_qsw [NN * 128];
__device__ __align__(16) float  g_wrow[NN * HH * 128];

__device__ __forceinline__ uint32_t smem_u32(const void* p) {
    uint32_t a;
    asm("{ .reg .u64 t; cvta.to.shared.u64 t, %1; cvt.u32.u64 %0, t; }" : "=r"(a) : "l"(p));
    return a;
}
__device__ __forceinline__ void ldm4(uint32_t* r, uint32_t addr) {
    asm volatile("ldmatrix.sync.aligned.m8n8.x4.shared.b16 {%0,%1,%2,%3}, [%4];"
                 : "=r"(r[0]), "=r"(r[1]), "=r"(r[2]), "=r"(r[3]) : "r"(addr));
}
__device__ __forceinline__ void ldm4t(uint32_t* r, uint32_t addr) {
    asm volatile("ldmatrix.sync.aligned.m8n8.x4.trans.shared.b16 {%0,%1,%2,%3}, [%4];"
                 : "=r"(r[0]), "=r"(r[1]), "=r"(r[2]), "=r"(r[3]) : "r"(addr));
}
__device__ __forceinline__ void mma16(float* c, const uint32_t* a, const uint32_t* b) {
    asm volatile("mma.sync.aligned.m16n8k16.row.col.f32.f16.f16.f32 "
        "{%0,%1,%2,%3},{%4,%5,%6,%7},{%8,%9},{%0,%1,%2,%3};"
        : "+f"(c[0]), "+f"(c[1]), "+f"(c[2]), "+f"(c[3])
        : "r"(a[0]), "r"(a[1]), "r"(a[2]), "r"(a[3]), "r"(b[0]), "r"(b[1]));
}
#define CPA16(dst, src) \
    asm volatile("cp.async.cg.shared.global [%0], [%1], 16;" :: "r"(dst), "l"(src) : "memory")

// ============================================================================
// generic fp16 GEMM: block 128x128, 8 warps (64x32), ktile 64, 3-stage.
// MODE: 1=dots(split-K=2), 2=O trans-B, 3=out, 4=ksw (fused sw-reduce)
// ============================================================================
template<int MODE, int KT>
__global__ __launch_bounds__(256) void g16(const float* __restrict__ auxA,
                                           float* __restrict__ outp) {
    extern __shared__ __half sh[];
    __half* AsB = sh;
    __half* BsB = sh + 3 * ASTG_H;
    const int t = threadIdx.x, lane = t & 31, warp = t >> 5;
    const int bx = blockIdx.x, by = blockIdx.y;
    const int h = (MODE == 1) ? (blockIdx.z & 7) : blockIdx.z;
    const int split = (MODE == 1) ? (blockIdx.z >> 3) : 0;

    const __half *A, *B; int lda, ldb;
    if (MODE == 4)      { A = g_xh + (size_t)by * 128 * 128; lda = 128;
                          B = g_wt + (size_t)768 * 128;      ldb = 128; }
    else if (MODE == 1) { A = g_qh + ((size_t)h * 512 + by * 128) * 4096 + split * 2048; lda = 4096;
                          B = g_kh + ((size_t)h * 512 + bx * 128) * 4096 + split * 2048; ldb = 4096; }
    else if (MODE == 2) { A = g_ph + ((size_t)h * 512 + by * 128) * 512; lda = 512;
                          B = g_vh + (size_t)h * 512 * 4096 + bx * 128;  ldb = 4096; }
    else                { A = g_o2 + (size_t)by * 128 * 256; lda = 256;
                          B = g_woutt;                       ldb = 256; }

    auto cpst = [&](int st, int k0) {
        uint32_t da = smem_u32(AsB + st * ASTG_H), db = smem_u32(BsB + st * ASTG_H);
#pragma unroll
        for (int c = t; c < 1024; c += 256) {
            int row = c >> 3, col = c & 7;
            CPA16(da + row * 144 + col * 16, A + (size_t)row * lda + k0 + col * 8);
        }
        if (MODE == 2) {
#pragma unroll
            for (int c = t; c < 1024; c += 256) {
                int row = c >> 4, col = c & 15;
                CPA16(db + row * 272 + col * 16, B + (size_t)(k0 + row) * ldb + col * 8);
            }
        } else {
#pragma unroll
            for (int c = t; c < 1024; c += 256) {
                int row = c >> 3, col = c & 7;
                CPA16(db + row * 144 + col * 16, B + (size_t)row * ldb + k0 + col * 8);
            }
        }
        asm volatile("cp.async.commit_group;" ::: "memory");
    };

    float acc[4][4][4] = {};
    const int wm0 = (warp >> 2) * 64, wn0 = (warp & 3) * 32;
    const int q = lane >> 3;

    cpst(0, 0);
    if (KT > 1) cpst(1, 64);
    int st = 0;
    for (int kt = 0; kt < KT; kt++) {
        if (kt + 1 < KT) asm volatile("cp.async.wait_group 1;" ::: "memory");
        else             asm volatile("cp.async.wait_group 0;" ::: "memory");
        __syncthreads();
        uint32_t ab = smem_u32(AsB + st * ASTG_H), bb = smem_u32(BsB + st * ASTG_H);
#pragma unroll
        for (int kk = 0; kk < 64; kk += 16) {
            uint32_t af[4][4], bf[2][4];
#pragma unroll
            for (int mt = 0; mt < 4; mt++)
                ldm4(af[mt], ab + (wm0 + mt * 16 + (lane & 15)) * 144 + (kk + (lane >> 4) * 8) * 2);
#pragma unroll
            for (int np = 0; np < 2; np++) {
                if (MODE == 2)
                    ldm4t(bf[np], bb + (kk + (q & 1) * 8 + (lane & 7)) * 272
                                     + (wn0 + np * 16 + (q >> 1) * 8) * 2);
                else
                    ldm4(bf[np], bb + (wn0 + np * 16 + (q >> 1) * 8 + (lane & 7)) * 144
                                    + (kk + (q & 1) * 8) * 2);
            }
#pragma unroll
            for (int mt = 0; mt < 4; mt++)
#pragma unroll
                for (int nt = 0; nt < 4; nt++)
                    mma16(acc[mt][nt], af[mt], &bf[nt >> 1][(nt & 1) * 2]);
        }
        if (kt + 2 < KT) {
            int ns = st + 2; if (ns >= 3) ns -= 3;
            cpst(ns, (kt + 2) * 64);
        }
        st = (st == 2) ? 0 : st + 1;
    }

    if (MODE == 4) {
#pragma unroll
        for (int mt = 0; mt < 4; mt++)
#pragma unroll
            for (int hf = 0; hf < 2; hf++) {
                int mrow = wm0 + mt * 16 + (lane >> 2) + hf * 8;
                int m = by * 128 + mrow, r = m >> 9, n = m & 511;
                float p[2] = {0.f, 0.f};
#pragma unroll
                for (int nt = 0; nt < 4; nt++) {
                    int c = wn0 + nt * 8 + (lane & 3) * 2;
                    float v0 = acc[mt][nt][hf * 2]     + auxA[c];
                    float v1 = acc[mt][nt][hf * 2 + 1] + auxA[c + 1];
                    p[nt >> 1] += v0 * g_qsw[n * 128 + c] + v1 * g_qsw[n * 128 + c + 1];
                }
#pragma unroll
                for (int hi = 0; hi < 2; hi++) {
                    p[hi] += __shfl_xor_sync(0xffffffffu, p[hi], 1);
                    p[hi] += __shfl_xor_sync(0xffffffffu, p[hi], 2);
                }
                if ((lane & 3) == 0) {
                    int h0 = wn0 >> 4;
                    g_wrow[(n * 8 + h0) * 128 + r]     = p[0] * 0.25f;
                    g_wrow[(n * 8 + h0 + 1) * 128 + r] = p[1] * 0.25f;
                }
            }
        return;
    }

#pragma unroll
    for (int mt = 0; mt < 4; mt++)
#pragma unroll
        for (int nt = 0; nt < 4; nt++)
#pragma unroll
            for (int hf = 0; hf < 2; hf++) {
                int mrow = wm0 + mt * 16 + (lane >> 2) + hf * 8;
                int ncol = wn0 + nt * 8 + (lane & 3) * 2;
                float v0 = acc[mt][nt][hf * 2], v1 = acc[mt][nt][hf * 2 + 1];
                if (MODE == 1) {
                    int i = by * 128 + mrow, j = bx * 128 + ncol;
                    size_t off = (size_t)split * DPL + ((size_t)h * 512 + i) * 512 + j;
                    g_dots[off]     = v0;
                    g_dots[off + 1] = v1;
                } else if (MODE == 2) {
                    int i = by * 128 + mrow, tcol = bx * 128 + ncol;
                    int r = tcol >> 5, d = tcol & 31;
                    *reinterpret_cast<__half2*>(
                        &g_o2[((size_t)r * 512 + i) * 256 + h * 32 + d]) =
                        __floats2half2_rn(v0, v1);
                } else {
                    int m = by * 128 + mrow;
                    outp[(size_t)m * 128 + ncol]     = v0 + auxA[ncol];
                    outp[(size_t)m * 128 + ncol + 1] = v1 + auxA[ncol + 1];
                }
            }
}

// ============================================================================
// qkv: one CTA per 128-row block; A staged once; 6 weight tiles, 3-stage B.
// ============================================================================
__global__ __launch_bounds__(256) void qkv6() {
    extern __shared__ __half sh[];
    __half* AsB = sh;
    __half* BsB = sh + 2 * ASTG_H;
    const int t = threadIdx.x, lane = t & 31, warp = t >> 5;
    const int by = blockIdx.y;
    const __half* A = g_xh + (size_t)by * 128 * 128;

#pragma unroll
    for (int kt = 0; kt < 2; kt++) {
        uint32_t da = smem_u32(AsB + kt * ASTG_H);
#pragma unroll
        for (int c = t; c < 1024; c += 256) {
            int row = c >> 3, col = c & 7;
            CPA16(da + row * 144 + col * 16, A + (size_t)row * 128 + kt * 64 + col * 8);
        }
    }
    asm volatile("cp.async.commit_group;" ::: "memory");

    auto cpB = [&](int st, int it) {
        const __half* B = g_wt + (size_t)(it >> 1) * 128 * 128 + (it & 1) * 64;
        uint32_t db = smem_u32(BsB + st * ASTG_H);
#pragma unroll
        for (int c = t; c < 1024; c += 256) {
            int row = c >> 3, col = c & 7;
            CPA16(db + row * 144 + col * 16, B + (size_t)row * 128 + col * 8);
        }
        asm volatile("cp.async.commit_group;" ::: "memory");
    };

    cpB(0, 0);
    cpB(1, 1);
    float acc[4][4][4] = {};
    const int wm0 = (warp >> 2) * 64, wn0 = (warp & 3) * 32;
    const int q = lane >> 3;

    int st = 0;
    for (int it = 0; it < 12; it++) {
        if (it + 1 < 12) asm volatile("cp.async.wait_group 1;" ::: "memory");
        else             asm volatile("cp.async.wait_group 0;" ::: "memory");
        __syncthreads();
        if (it + 2 < 12) {
            int ns = st + 2; if (ns >= 3) ns -= 3;
            cpB(ns, it + 2);
        }
        uint32_t ab = smem_u32(AsB + (it & 1) * ASTG_H), bb = smem_u32(BsB + st * ASTG_H);
#pragma unroll
        for (int kk = 0; kk < 64; kk += 16) {
            uint32_t af[4][4], bf[2][4];
#pragma unroll
            for (int mt = 0; mt < 4; mt++)
                ldm4(af[mt], ab + (wm0 + mt * 16 + (lane & 15)) * 144 + (kk + (lane >> 4) * 8) * 2);
#pragma unroll
            for (int np = 0; np < 2; np++)
                ldm4(bf[np], bb + (wn0 + np * 16 + (q >> 1) * 8 + (lane & 7)) * 144
                                + (kk + (q & 1) * 8) * 2);
#pragma unroll
            for (int mt = 0; mt < 4; mt++)
#pragma unroll
                for (int nt = 0; nt < 4; nt++)
                    mma16(acc[mt][nt], af[mt], &bf[nt >> 1][(nt & 1) * 2]);
        }
        st = (st == 2) ? 0 : st + 1;

        if (it & 1) {
            const int cb = it >> 1;
#pragma unroll
            for (int mt = 0; mt < 4; mt++)
#pragma unroll
                for (int nt = 0; nt < 4; nt++)
#pragma unroll
                    for (int hf = 0; hf < 2; hf++) {
                        int mrow = wm0 + mt * 16 + (lane >> 2) + hf * 8;
                        int ncol = wn0 + nt * 8 + (lane & 3) * 2;
                        int m = by * 128 + mrow, c = cb * 128 + ncol;
                        int r = m >> 9, n = m & 511;
                        float v0 = acc[mt][nt][hf * 2], v1 = acc[mt][nt][hf * 2 + 1];
                        if (c < 256) {
                            int hh = c >> 5, d = c & 31;
                            float w = g_wrow[(n * 8 + hh) * 128 + r];
                            *reinterpret_cast<__half2*>(
                                &g_qh[((size_t)(hh * 512 + n)) * 4096 + r * 32 + d]) =
                                __floats2half2_rn(v0 * w, v1 * w);
                        } else if (c < 512) {
                            int cc = c - 256, hh = cc >> 5, d = cc & 31;
                            *reinterpret_cast<__half2*>(
                                &g_kh[((size_t)(hh * 512 + n)) * 4096 + r * 32 + d]) =
                                __floats2half2_rn(v0, v1);
                        } else {
                            int cc = c - 512, hh = cc >> 5, d = cc & 31;
                            *reinterpret_cast<__half2*>(
                                &g_vh[((size_t)(hh * 512 + n)) * 4096 + r * 32 + d]) =
                                __floats2half2_rn(v0, v1);
                        }
                        acc[mt][nt][hf * 2] = 0.f;
                        acc[mt][nt][hf * 2 + 1] = 0.f;
                    }
        }
    }
}

// ============================================================================
// pbh: warp per 4 consecutive rows; split-tree head reduce; float4 stores.
// ============================================================================
__global__ __launch_bounds__(256) void pbh_kernel(const float* __restrict__ pair_bias,
                                                  const float* __restrict__ ln_g,
                                                  const float* __restrict__ ln_b,
                                                  const float* __restrict__ Wpair) {
    const int lane = threadIdx.x & 31;
    const int gw = (blockIdx.x * 256 + threadIdx.x) >> 5;
    const int nw = (gridDim.x * 256) >> 5;
    const int p0 = lane * 4;

    float gg[4], bb4[4], wp[4][8];
#pragma unroll
    for (int e = 0; e < 4; e++) {
        gg[e]  = ln_g[p0 + e];
        bb4[e] = ln_b[p0 + e];
        float4 w0 = *reinterpret_cast<const float4*>(&Wpair[(p0 + e) * 8]);
        float4 w1 = *reinterpret_cast<const float4*>(&Wpair[(p0 + e) * 8 + 4]);
        wp[e][0] = w0.x; wp[e][1] = w0.y; wp[e][2] = w0.z; wp[e][3] = w0.w;
        wp[e][4] = w1.x; wp[e][5] = w1.y; wp[e][6] = w1.z; wp[e][7] = w1.w;
    }
    const int myh = ((lane >> 4) & 1) * 4 + ((lane >> 3) & 1) * 2 + ((lane >> 2) & 1);
    const bool writer = (lane & 3) == 0;

    for (int idx = gw * 4; idx < NN * NN; idx += nw * 4) {
        float vv[4][4];
        float s[4], sq[4];
#pragma unroll
        for (int rr = 0; rr < 4; rr++) {
            float4 v = *reinterpret_cast<const float4*>(&pair_bias[(size_t)(idx + rr) * 128 + p0]);
            vv[rr][0] = v.x; vv[rr][1] = v.y; vv[rr][2] = v.z; vv[rr][3] = v.w;
            s[rr]  = v.x + v.y + v.z + v.w;
            sq[rr] = v.x * v.x + v.y * v.y + v.z * v.z + v.w * v.w;
        }
#pragma unroll
        for (int o = 16; o; o >>= 1) {
#pragma unroll
            for (int rr = 0; rr < 4; rr++) {
                s[rr]  += __shfl_xor_sync(0xffffffffu, s[rr], o);
                sq[rr] += __shfl_xor_sync(0xffffffffu, sq[rr], o);
            }
        }
        float res[4];
#pragma unroll
        for (int rr = 0; rr < 4; rr++) {
            float mean = s[rr] * (1.0f / 128.0f);
            float var  = sq[rr] * (1.0f / 128.0f) - mean * mean;
            float rstd = rsqrtf(var + 1e-5f);
            float v[8] = {};
#pragma unroll
            for (int e = 0; e < 4; e++) {
                float nz = (vv[rr][e] - mean) * rstd * gg[e] + bb4[e];
#pragma unroll
                for (int hh = 0; hh < 8; hh++) v[hh] += nz * wp[e][hh];
            }
#pragma unroll
            for (int hh = 0; hh < 8; hh++) v[hh] += __shfl_xor_sync(0xffffffffu, v[hh], 16);
            if (lane & 16) { v[0] = v[4]; v[1] = v[5]; v[2] = v[6]; v[3] = v[7]; }
#pragma unroll
            for (int hh = 0; hh < 4; hh++) v[hh] += __shfl_xor_sync(0xffffffffu, v[hh], 8);
            if (lane & 8) { v[0] = v[2]; v[1] = v[3]; }
#pragma unroll
            for (int hh = 0; hh < 2; hh++) v[hh] += __shfl_xor_sync(0xffffffffu, v[hh], 4);
            if (lane & 4) { v[0] = v[1]; }
            v[0] += __shfl_xor_sync(0xffffffffu, v[0], 2);
            v[0] += __shfl_xor_sync(0xffffffffu, v[0], 1);
            res[rr] = v[0];
        }
        if (writer) {
            int i = idx >> 9, j0 = idx & 511;
            *reinterpret_cast<float4*>(&g_pbh[(((size_t)myh << 9) + i) * NN + j0]) =
                make_float4(res[0], res[1], res[2], res[3]);
        }
    }
}

// ============================================================================
__global__ void conv_x(const float* __restrict__ x) {
    size_t i = ((size_t)blockIdx.x * 256 + threadIdx.x) * 4;
    float4 v = *reinterpret_cast<const float4*>(x + i);
    __half2* d = reinterpret_cast<__half2*>(&g_xh[i]);
    d[0] = __floats2half2_rn(v.x, v.y);
    d[1] = __floats2half2_rn(v.z, v.w);
}

__global__ void conv_w(const float* __restrict__ Wq, const float* __restrict__ Wkv,
                       const float* __restrict__ Wk_sw, const float* __restrict__ Wout) {
    int g = blockIdx.x * 256 + threadIdx.x;
    if (g < 114688) {
        int row = g >> 7, k = g & 127;
        float v;
        if (row < 256)      v = Wq[k * 256 + row];
        else if (row < 768) v = Wkv[k * 512 + (row - 256)];
        else                v = Wk_sw[k * 128 + (row - 768)];
        g_wt[g] = __float2half_rn(v);
    } else {
        int g2 = g - 114688;
        int c = g2 >> 8, k = g2 & 255;
        g_woutt[g2] = __float2half_rn(Wout[k * 128 + c]);
    }
}

__global__ void qsw_kernel(const float* __restrict__ x, const float* __restrict__ Wq_sw,
                           const float* __restrict__ bq_sw) {
    int n = blockIdx.x, c = threadIdx.x;
    __shared__ float xr[128];
    xr[c] = x[(size_t)n * 128 + c];
    __syncthreads();
    float acc = bq_sw[c];
#pragma unroll 8
    for (int k = 0; k < 128; k++) acc += xr[k] * Wq_sw[k * 128 + c];
    g_qsw[n * 128 + c] = acc;
}

__global__ void wrow_softmax_kernel() {
    int row = blockIdx.x, t = threadIdx.x;
    float v = g_wrow[(size_t)row * 128 + t];
    __shared__ float sm[128];
    sm[t] = v; __syncthreads();
#pragma unroll
    for (int s = 64; s > 0; s >>= 1) { if (t < s) sm[t] = fmaxf(sm[t], sm[t + s]); __syncthreads(); }
    float mx = sm[0]; __syncthreads();
    float e = expf(v - mx);
    sm[t] = e; __syncthreads();
#pragma unroll
    for (int s = 64; s > 0; s >>= 1) { if (t < s) sm[t] += sm[t + s]; __syncthreads(); }
    g_wrow[(size_t)row * 128 + t] = e / sm[0];
}

__global__ void attn_softmax_kernel() {
    size_t row = blockIdx.x;
    int t = threadIdx.x;
    size_t off0 = row * 512 + t, off1 = off0 + 256;
    const float scale = 0.17677669529663687f;
    float v0 = (g_dots[off0] + g_dots[off0 + DPL]) * scale + g_pbh[off0];
    float v1 = (g_dots[off1] + g_dots[off1 + DPL]) * scale + g_pbh[off1];
    __shared__ float sm[256];
    sm[t] = fmaxf(v0, v1); __syncthreads();
#pragma unroll
    for (int s = 128; s > 0; s >>= 1) { if (t < s) sm[t] = fmaxf(sm[t], sm[t + s]); __syncthreads(); }
    float mx = sm[0]; __syncthreads();
    float e0 = expf(v0 - mx), e1 = expf(v1 - mx);
    sm[t] = e0 + e1; __syncthreads();
#pragma unroll
    for (int s = 128; s > 0; s >>= 1) { if (t < s) sm[t] += sm[t + s]; __syncthreads(); }
    float inv = 1.0f / sm[0];
    g_ph[row * 512 + t]       = __float2half_rn(e0 * inv);
    g_ph[row * 512 + t + 256] = __float2half_rn(e1 * inv);
}

// ============================================================================
extern "C" void kernel_launch(void* const* d_in, const int* in_sizes, int n_in,
                              void* d_out, int out_size) {
    (void)in_sizes; (void)n_in; (void)out_size;
    const float* x         = (const float*)d_in[0];
    const float* pair_bias = (const float*)d_in[1];
    const float* Wq        = (const float*)d_in[2];
    const float* Wkv       = (const float*)d_in[3];
    const float* Wout      = (const float*)d_in[4];
    const float* b_out     = (const float*)d_in[5];
    const float* ln_g      = (const float*)d_in[6];
    const float* ln_b      = (const float*)d_in[7];
    const float* Wpair     = (const float*)d_in[8];
    const float* Wq_sw     = (const float*)d_in[9];
    const float* bq_sw     = (const float*)d_in[10];
    const float* Wk_sw     = (const float*)d_in[11];
    const float* bk_sw     = (const float*)d_in[12];
    float* out = (float*)d_out;

    static int init_done = 0;
    static cudaStream_t s1;
    static cudaEvent_t e0, e1;
    if (!init_done) {
        cudaFuncSetAttribute(qkv6,       cudaFuncAttributeMaxDynamicSharedMemorySize, SMEM_QKV);
        cudaFuncSetAttribute(g16<1, 32>, cudaFuncAttributeMaxDynamicSharedMemorySize, SMEM_BYTES);
        cudaFuncSetAttribute(g16<2, 8>,  cudaFuncAttributeMaxDynamicSharedMemorySize, SMEM_BYTES);
        cudaFuncSetAttribute(g16<3, 4>,  cudaFuncAttributeMaxDynamicSharedMemorySize, SMEM_BYTES);
        cudaFuncSetAttribute(g16<4, 2>,  cudaFuncAttributeMaxDynamicSharedMemorySize, SMEM_BYTES);
        cudaStreamCreateWithFlags(&s1, cudaStreamNonBlocking);
        cudaEventCreateWithFlags(&e0, cudaEventDisableTiming);
        cudaEventCreateWithFlags(&e1, cudaEventDisableTiming);
        init_done = 1;
    }

    // fork: pbh runs on s1 concurrently with the main GEMM chain
    cudaEventRecord(e0, 0);
    cudaStreamWaitEvent(s1, e0, 0);
    pbh_kernel<<<2048, 256, 0, s1>>>(pair_bias, ln_g, ln_b, Wpair);
    cudaEventRecord(e1, s1);

    // main chain (default stream)
    conv_x             <<<8192, 256>>>(x);
    conv_w             <<<576, 256>>>(Wq, Wkv, Wk_sw, Wout);
    qsw_kernel         <<<NN, 128>>>(x, Wq_sw, bq_sw);
    g16<4, 2>          <<<dim3(1, 512), 256, SMEM_BYTES>>>(bk_sw, nullptr);  // ksw + fused reduce
    wrow_softmax_kernel<<<NN * HH, 128>>>();
    qkv6               <<<dim3(1, 512), 256, SMEM_QKV>>>();
    g16<1, 32>         <<<dim3(4, 4, 16), 256, SMEM_BYTES>>>(nullptr, nullptr); // dots sK=2

    // join: attn_softmax needs g_pbh
    cudaStreamWaitEvent(0, e1, 0);
    attn_softmax_kernel<<<HH * NN, 256>>>();
    g16<2, 8>          <<<dim3(32, 4, 8), 256, SMEM_BYTES>>>(nullptr, nullptr); // O
    g16<3, 4>          <<<dim3(1, 512), 256, SMEM_BYTES>>>(b_out, out);         // out
}

// round 17
// speedup vs baseline: 1.1111x; 1.0568x over previous
#include <cuda_runtime.h>
#include <cuda_fp16.h>
#include <cstdint>

#define NN 512
#define HH 8
#define RDC 4096
#define MRN 65536
#define DPL 2097152    // one dots plane
#define ASTG_H 9216    // halves per smem stage (128 rows * 144B)
#define SMEM_BYTES 110592
#define SMEM_QKV 92160

__device__ __align__(16) __half g_xh  [MRN * 128];
__device__ __align__(16) __half g_wt  [896 * 128];
__device__ __align__(16) __half g_woutt[128 * 256];
__device__ __align__(16) __half g_qh  [HH * NN * RDC];
__device__ __align__(16) __half g_kh  [HH * NN * RDC];
__device__ __align__(16) __half g_vh  [HH * NN * RDC];
__device__ __align__(16) __half g_ph  [HH * NN * NN];
__device__ __align__(16) __half g_o2  [MRN * 256];
__device__ __align__(16) float  g_dots[2 * DPL];
__device__ __align__(16) float  g_pbh [HH * NN * NN];
__device__ __align__(16) float  g_qsw [NN * 128];
__device__ __align__(16) float  g_wrow[NN * HH * 128];

__device__ __forceinline__ uint32_t smem_u32(const void* p) {
    uint32_t a;
    asm("{ .reg .u64 t; cvta.to.shared.u64 t, %1; cvt.u32.u64 %0, t; }" : "=r"(a) : "l"(p));
    return a;
}
__device__ __forceinline__ void ldm4(uint32_t* r, uint32_t addr) {
    asm volatile("ldmatrix.sync.aligned.m8n8.x4.shared.b16 {%0,%1,%2,%3}, [%4];"
                 : "=r"(r[0]), "=r"(r[1]), "=r"(r[2]), "=r"(r[3]) : "r"(addr));
}
__device__ __forceinline__ void ldm4t(uint32_t* r, uint32_t addr) {
    asm volatile("ldmatrix.sync.aligned.m8n8.x4.trans.shared.b16 {%0,%1,%2,%3}, [%4];"
                 : "=r"(r[0]), "=r"(r[1]), "=r"(r[2]), "=r"(r[3]) : "r"(addr));
}
__device__ __forceinline__ void mma16(float* c, const uint32_t* a, const uint32_t* b) {
    asm volatile("mma.sync.aligned.m16n8k16.row.col.f32.f16.f16.f32 "
        "{%0,%1,%2,%3},{%4,%5,%6,%7},{%8,%9},{%0,%1,%2,%3};"
        : "+f"(c[0]), "+f"(c[1]), "+f"(c[2]), "+f"(c[3])
        : "r"(a[0]), "r"(a[1]), "r"(a[2]), "r"(a[3]), "r"(b[0]), "r"(b[1]));
}
#define CPA16(dst, src) \
    asm volatile("cp.async.cg.shared.global [%0], [%1], 16;" :: "r"(dst), "l"(src) : "memory")

// ============================================================================
// generic fp16 GEMM: block 128x128, 8 warps (64x32), ktile 64, 3-stage.
// MODE: 1=dots(split-K=2), 2=O trans-B, 3=out, 4=ksw (fused sw-reduce)
// ============================================================================
template<int MODE, int KT>
__global__ __launch_bounds__(256) void g16(const float* __restrict__ auxA,
                                           float* __restrict__ outp) {
    extern __shared__ __half sh[];
    __half* AsB = sh;
    __half* BsB = sh + 3 * ASTG_H;
    const int t = threadIdx.x, lane = t & 31, warp = t >> 5;
    const int bx = blockIdx.x, by = blockIdx.y;
    const int h = (MODE == 1) ? (blockIdx.z & 7) : blockIdx.z;
    const int split = (MODE == 1) ? (blockIdx.z >> 3) : 0;

    const __half *A, *B; int lda, ldb;
    if (MODE == 4)      { A = g_xh + (size_t)by * 128 * 128; lda = 128;
                          B = g_wt + (size_t)768 * 128;      ldb = 128; }
    else if (MODE == 1) { A = g_qh + ((size_t)h * 512 + by * 128) * 4096 + split * 2048; lda = 4096;
                          B = g_kh + ((size_t)h * 512 + bx * 128) * 4096 + split * 2048; ldb = 4096; }
    else if (MODE == 2) { A = g_ph + ((size_t)h * 512 + by * 128) * 512; lda = 512;
                          B = g_vh + (size_t)h * 512 * 4096 + bx * 128;  ldb = 4096; }
    else                { A = g_o2 + (size_t)by * 128 * 256; lda = 256;
                          B = g_woutt;                       ldb = 256; }

    auto cpst = [&](int st, int k0) {
        uint32_t da = smem_u32(AsB + st * ASTG_H), db = smem_u32(BsB + st * ASTG_H);
#pragma unroll
        for (int c = t; c < 1024; c += 256) {
            int row = c >> 3, col = c & 7;
            CPA16(da + row * 144 + col * 16, A + (size_t)row * lda + k0 + col * 8);
        }
        if (MODE == 2) {
#pragma unroll
            for (int c = t; c < 1024; c += 256) {
                int row = c >> 4, col = c & 15;
                CPA16(db + row * 272 + col * 16, B + (size_t)(k0 + row) * ldb + col * 8);
            }
        } else {
#pragma unroll
            for (int c = t; c < 1024; c += 256) {
                int row = c >> 3, col = c & 7;
                CPA16(db + row * 144 + col * 16, B + (size_t)row * ldb + k0 + col * 8);
            }
        }
        asm volatile("cp.async.commit_group;" ::: "memory");
    };

    float acc[4][4][4] = {};
    const int wm0 = (warp >> 2) * 64, wn0 = (warp & 3) * 32;
    const int q = lane >> 3;

    cpst(0, 0);
    if (KT > 1) cpst(1, 64);
    int st = 0;
    for (int kt = 0; kt < KT; kt++) {
        if (kt + 1 < KT) asm volatile("cp.async.wait_group 1;" ::: "memory");
        else             asm volatile("cp.async.wait_group 0;" ::: "memory");
        __syncthreads();
        uint32_t ab = smem_u32(AsB + st * ASTG_H), bb = smem_u32(BsB + st * ASTG_H);
#pragma unroll
        for (int kk = 0; kk < 64; kk += 16) {
            uint32_t af[4][4], bf[2][4];
#pragma unroll
            for (int mt = 0; mt < 4; mt++)
                ldm4(af[mt], ab + (wm0 + mt * 16 + (lane & 15)) * 144 + (kk + (lane >> 4) * 8) * 2);
#pragma unroll
            for (int np = 0; np < 2; np++) {
                if (MODE == 2)
                    ldm4t(bf[np], bb + (kk + (q & 1) * 8 + (lane & 7)) * 272
                                     + (wn0 + np * 16 + (q >> 1) * 8) * 2);
                else
                    ldm4(bf[np], bb + (wn0 + np * 16 + (q >> 1) * 8 + (lane & 7)) * 144
                                    + (kk + (q & 1) * 8) * 2);
            }
#pragma unroll
            for (int mt = 0; mt < 4; mt++)
#pragma unroll
                for (int nt = 0; nt < 4; nt++)
                    mma16(acc[mt][nt], af[mt], &bf[nt >> 1][(nt & 1) * 2]);
        }
        if (kt + 2 < KT) {
            int ns = st + 2; if (ns >= 3) ns -= 3;
            cpst(ns, (kt + 2) * 64);
        }
        st = (st == 2) ? 0 : st + 1;
    }

    if (MODE == 4) {
#pragma unroll
        for (int mt = 0; mt < 4; mt++)
#pragma unroll
            for (int hf = 0; hf < 2; hf++) {
                int mrow = wm0 + mt * 16 + (lane >> 2) + hf * 8;
                int m = by * 128 + mrow, r = m >> 9, n = m & 511;
                float p[2] = {0.f, 0.f};
#pragma unroll
                for (int nt = 0; nt < 4; nt++) {
                    int c = wn0 + nt * 8 + (lane & 3) * 2;
                    float v0 = acc[mt][nt][hf * 2]     + auxA[c];
                    float v1 = acc[mt][nt][hf * 2 + 1] + auxA[c + 1];
                    p[nt >> 1] += v0 * g_qsw[n * 128 + c] + v1 * g_qsw[n * 128 + c + 1];
                }
#pragma unroll
                for (int hi = 0; hi < 2; hi++) {
                    p[hi] += __shfl_xor_sync(0xffffffffu, p[hi], 1);
                    p[hi] += __shfl_xor_sync(0xffffffffu, p[hi], 2);
                }
                if ((lane & 3) == 0) {
                    int h0 = wn0 >> 4;
                    g_wrow[(n * 8 + h0) * 128 + r]     = p[0] * 0.25f;
                    g_wrow[(n * 8 + h0 + 1) * 128 + r] = p[1] * 0.25f;
                }
            }
        return;
    }

#pragma unroll
    for (int mt = 0; mt < 4; mt++)
#pragma unroll
        for (int nt = 0; nt < 4; nt++)
#pragma unroll
            for (int hf = 0; hf < 2; hf++) {
                int mrow = wm0 + mt * 16 + (lane >> 2) + hf * 8;
                int ncol = wn0 + nt * 8 + (lane & 3) * 2;
                float v0 = acc[mt][nt][hf * 2], v1 = acc[mt][nt][hf * 2 + 1];
                if (MODE == 1) {
                    int i = by * 128 + mrow, j = bx * 128 + ncol;
                    size_t off = (size_t)split * DPL + ((size_t)h * 512 + i) * 512 + j;
                    g_dots[off]     = v0;
                    g_dots[off + 1] = v1;
                } else if (MODE == 2) {
                    int i = by * 128 + mrow, tcol = bx * 128 + ncol;
                    int r = tcol >> 5, d = tcol & 31;
                    *reinterpret_cast<__half2*>(
                        &g_o2[((size_t)r * 512 + i) * 256 + h * 32 + d]) =
                        __floats2half2_rn(v0, v1);
                } else {
                    int m = by * 128 + mrow;
                    outp[(size_t)m * 128 + ncol]     = v0 + auxA[ncol];
                    outp[(size_t)m * 128 + ncol + 1] = v1 + auxA[ncol + 1];
                }
            }
}

// ============================================================================
// qkv: one CTA per 128-row block; A staged once; 6 weight tiles, 3-stage B.
// ============================================================================
__global__ __launch_bounds__(256) void qkv6() {
    extern __shared__ __half sh[];
    __half* AsB = sh;
    __half* BsB = sh + 2 * ASTG_H;
    const int t = threadIdx.x, lane = t & 31, warp = t >> 5;
    const int by = blockIdx.y;
    const __half* A = g_xh + (size_t)by * 128 * 128;

#pragma unroll
    for (int kt = 0; kt < 2; kt++) {
        uint32_t da = smem_u32(AsB + kt * ASTG_H);
#pragma unroll
        for (int c = t; c < 1024; c += 256) {
            int row = c >> 3, col = c & 7;
            CPA16(da + row * 144 + col * 16, A + (size_t)row * 128 + kt * 64 + col * 8);
        }
    }
    asm volatile("cp.async.commit_group;" ::: "memory");

    auto cpB = [&](int st, int it) {
        const __half* B = g_wt + (size_t)(it >> 1) * 128 * 128 + (it & 1) * 64;
        uint32_t db = smem_u32(BsB + st * ASTG_H);
#pragma unroll
        for (int c = t; c < 1024; c += 256) {
            int row = c >> 3, col = c & 7;
            CPA16(db + row * 144 + col * 16, B + (size_t)row * 128 + col * 8);
        }
        asm volatile("cp.async.commit_group;" ::: "memory");
    };

    cpB(0, 0);
    cpB(1, 1);
    float acc[4][4][4] = {};
    const int wm0 = (warp >> 2) * 64, wn0 = (warp & 3) * 32;
    const int q = lane >> 3;

    int st = 0;
    for (int it = 0; it < 12; it++) {
        if (it + 1 < 12) asm volatile("cp.async.wait_group 1;" ::: "memory");
        else             asm volatile("cp.async.wait_group 0;" ::: "memory");
        __syncthreads();
        if (it + 2 < 12) {
            int ns = st + 2; if (ns >= 3) ns -= 3;
            cpB(ns, it + 2);
        }
        uint32_t ab = smem_u32(AsB + (it & 1) * ASTG_H), bb = smem_u32(BsB + st * ASTG_H);
#pragma unroll
        for (int kk = 0; kk < 64; kk += 16) {
            uint32_t af[4][4], bf[2][4];
#pragma unroll
            for (int mt = 0; mt < 4; mt++)
                ldm4(af[mt], ab + (wm0 + mt * 16 + (lane & 15)) * 144 + (kk + (lane >> 4) * 8) * 2);
#pragma unroll
            for (int np = 0; np < 2; np++)
                ldm4(bf[np], bb + (wn0 + np * 16 + (q >> 1) * 8 + (lane & 7)) * 144
                                + (kk + (q & 1) * 8) * 2);
#pragma unroll
            for (int mt = 0; mt < 4; mt++)
#pragma unroll
                for (int nt = 0; nt < 4; nt++)
                    mma16(acc[mt][nt], af[mt], &bf[nt >> 1][(nt & 1) * 2]);
        }
        st = (st == 2) ? 0 : st + 1;

        if (it & 1) {
            const int cb = it >> 1;
#pragma unroll
            for (int mt = 0; mt < 4; mt++)
#pragma unroll
                for (int nt = 0; nt < 4; nt++)
#pragma unroll
                    for (int hf = 0; hf < 2; hf++) {
                        int mrow = wm0 + mt * 16 + (lane >> 2) + hf * 8;
                        int ncol = wn0 + nt * 8 + (lane & 3) * 2;
                        int m = by * 128 + mrow, c = cb * 128 + ncol;
                        int r = m >> 9, n = m & 511;
                        float v0 = acc[mt][nt][hf * 2], v1 = acc[mt][nt][hf * 2 + 1];
                        if (c < 256) {
                            int hh = c >> 5, d = c & 31;
                            float w = g_wrow[(n * 8 + hh) * 128 + r];
                            *reinterpret_cast<__half2*>(
                                &g_qh[((size_t)(hh * 512 + n)) * 4096 + r * 32 + d]) =
                                __floats2half2_rn(v0 * w, v1 * w);
                        } else if (c < 512) {
                            int cc = c - 256, hh = cc >> 5, d = cc & 31;
                            *reinterpret_cast<__half2*>(
                                &g_kh[((size_t)(hh * 512 + n)) * 4096 + r * 32 + d]) =
                                __floats2half2_rn(v0, v1);
                        } else {
                            int cc = c - 512, hh = cc >> 5, d = cc & 31;
                            *reinterpret_cast<__half2*>(
                                &g_vh[((size_t)(hh * 512 + n)) * 4096 + r * 32 + d]) =
                                __floats2half2_rn(v0, v1);
                        }
                        acc[mt][nt][hf * 2] = 0.f;
                        acc[mt][nt][hf * 2 + 1] = 0.f;
                    }
        }
    }
}

// ============================================================================
// pbh: warp per 4 consecutive rows; split-tree head reduce; float4 stores.
// ============================================================================
__global__ __launch_bounds__(256) void pbh_kernel(const float* __restrict__ pair_bias,
                                                  const float* __restrict__ ln_g,
                                                  const float* __restrict__ ln_b,
                                                  const float* __restrict__ Wpair) {
    const int lane = threadIdx.x & 31;
    const int gw = (blockIdx.x * 256 + threadIdx.x) >> 5;
    const int nw = (gridDim.x * 256) >> 5;
    const int p0 = lane * 4;

    float gg[4], bb4[4], wp[4][8];
#pragma unroll
    for (int e = 0; e < 4; e++) {
        gg[e]  = ln_g[p0 + e];
        bb4[e] = ln_b[p0 + e];
        float4 w0 = *reinterpret_cast<const float4*>(&Wpair[(p0 + e) * 8]);
        float4 w1 = *reinterpret_cast<const float4*>(&Wpair[(p0 + e) * 8 + 4]);
        wp[e][0] = w0.x; wp[e][1] = w0.y; wp[e][2] = w0.z; wp[e][3] = w0.w;
        wp[e][4] = w1.x; wp[e][5] = w1.y; wp[e][6] = w1.z; wp[e][7] = w1.w;
    }
    const int myh = ((lane >> 4) & 1) * 4 + ((lane >> 3) & 1) * 2 + ((lane >> 2) & 1);
    const bool writer = (lane & 3) == 0;

    for (int idx = gw * 4; idx < NN * NN; idx += nw * 4) {
        float vv[4][4];
        float s[4], sq[4];
#pragma unroll
        for (int rr = 0; rr < 4; rr++) {
            float4 v = *reinterpret_cast<const float4*>(&pair_bias[(size_t)(idx + rr) * 128 + p0]);
            vv[rr][0] = v.x; vv[rr][1] = v.y; vv[rr][2] = v.z; vv[rr][3] = v.w;
            s[rr]  = v.x + v.y + v.z + v.w;
            sq[rr] = v.x * v.x + v.y * v.y + v.z * v.z + v.w * v.w;
        }
#pragma unroll
        for (int o = 16; o; o >>= 1) {
#pragma unroll
            for (int rr = 0; rr < 4; rr++) {
                s[rr]  += __shfl_xor_sync(0xffffffffu, s[rr], o);
                sq[rr] += __shfl_xor_sync(0xffffffffu, sq[rr], o);
            }
        }
        float res[4];
#pragma unroll
        for (int rr = 0; rr < 4; rr++) {
            float mean = s[rr] * (1.0f / 128.0f);
            float var  = sq[rr] * (1.0f / 128.0f) - mean * mean;
            float rstd = rsqrtf(var + 1e-5f);
            float v[8] = {};
#pragma unroll
            for (int e = 0; e < 4; e++) {
                float nz = (vv[rr][e] - mean) * rstd * gg[e] + bb4[e];
#pragma unroll
                for (int hh = 0; hh < 8; hh++) v[hh] += nz * wp[e][hh];
            }
#pragma unroll
            for (int hh = 0; hh < 8; hh++) v[hh] += __shfl_xor_sync(0xffffffffu, v[hh], 16);
            if (lane & 16) { v[0] = v[4]; v[1] = v[5]; v[2] = v[6]; v[3] = v[7]; }
#pragma unroll
            for (int hh = 0; hh < 4; hh++) v[hh] += __shfl_xor_sync(0xffffffffu, v[hh], 8);
            if (lane & 8) { v[0] = v[2]; v[1] = v[3]; }
#pragma unroll
            for (int hh = 0; hh < 2; hh++) v[hh] += __shfl_xor_sync(0xffffffffu, v[hh], 4);
            if (lane & 4) { v[0] = v[1]; }
            v[0] += __shfl_xor_sync(0xffffffffu, v[0], 2);
            v[0] += __shfl_xor_sync(0xffffffffu, v[0], 1);
            res[rr] = v[0];
        }
        if (writer) {
            int i = idx >> 9, j0 = idx & 511;
            *reinterpret_cast<float4*>(&g_pbh[(((size_t)myh << 9) + i) * NN + j0]) =
                make_float4(res[0], res[1], res[2], res[3]);
        }
    }
}

// ============================================================================
__global__ void conv_x(const float* __restrict__ x) {
    size_t i = ((size_t)blockIdx.x * 256 + threadIdx.x) * 4;
    float4 v = *reinterpret_cast<const float4*>(x + i);
    __half2* d = reinterpret_cast<__half2*>(&g_xh[i]);
    d[0] = __floats2half2_rn(v.x, v.y);
    d[1] = __floats2half2_rn(v.z, v.w);
}

__global__ void conv_w(const float* __restrict__ Wq, const float* __restrict__ Wkv,
                       const float* __restrict__ Wk_sw, const float* __restrict__ Wout) {
    int g = blockIdx.x * 256 + threadIdx.x;
    if (g < 114688) {
        int row = g >> 7, k = g & 127;
        float v;
        if (row < 256)      v = Wq[k * 256 + row];
        else if (row < 768) v = Wkv[k * 512 + (row - 256)];
        else                v = Wk_sw[k * 128 + (row - 768)];
        g_wt[g] = __float2half_rn(v);
    } else {
        int g2 = g - 114688;
        int c = g2 >> 8, k = g2 & 255;
        g_woutt[g2] = __float2half_rn(Wout[k * 128 + c]);
    }
}

// qsw: 4 independent accumulator chains, full unroll -> deep load pipelining
__global__ void qsw_kernel(const float* __restrict__ x, const float* __restrict__ Wq_sw,
                           const float* __restrict__ bq_sw) {
    int n = blockIdx.x, c = threadIdx.x;
    __shared__ float xr[128];
    xr[c] = x[(size_t)n * 128 + c];
    __syncthreads();
    float a0 = 0.f, a1 = 0.f, a2 = 0.f, a3 = 0.f;
#pragma unroll
    for (int k = 0; k < 128; k += 4) {
        a0 += xr[k]     * Wq_sw[k * 128 + c];
        a1 += xr[k + 1] * Wq_sw[(k + 1) * 128 + c];
        a2 += xr[k + 2] * Wq_sw[(k + 2) * 128 + c];
        a3 += xr[k + 3] * Wq_sw[(k + 3) * 128 + c];
    }
    g_qsw[n * 128 + c] = (a0 + a1) + (a2 + a3) + bq_sw[c];
}

// warp-per-row softmax over 128 values (w_row), no barriers
__global__ __launch_bounds__(256) void wrow_softmax_kernel() {
    int lane = threadIdx.x & 31, warp = threadIdx.x >> 5;
    int row = blockIdx.x * 8 + warp;           // 4096 rows
    float4 v = *reinterpret_cast<const float4*>(&g_wrow[(size_t)row * 128 + lane * 4]);
    float mx = fmaxf(fmaxf(v.x, v.y), fmaxf(v.z, v.w));
#pragma unroll
    for (int o = 16; o; o >>= 1) mx = fmaxf(mx, __shfl_xor_sync(0xffffffffu, mx, o));
    float e0 = expf(v.x - mx), e1 = expf(v.y - mx), e2 = expf(v.z - mx), e3 = expf(v.w - mx);
    float s = (e0 + e1) + (e2 + e3);
#pragma unroll
    for (int o = 16; o; o >>= 1) s += __shfl_xor_sync(0xffffffffu, s, o);
    float inv = 1.0f / s;
    *reinterpret_cast<float4*>(&g_wrow[(size_t)row * 128 + lane * 4]) =
        make_float4(e0 * inv, e1 * inv, e2 * inv, e3 * inv);
}

// warp-per-row softmax over 512 values (attn): combine split-K + pbh, no barriers
__global__ __launch_bounds__(256) void attn_softmax_kernel() {
    int lane = threadIdx.x & 31, warp = threadIdx.x >> 5;
    size_t row = (size_t)blockIdx.x * 8 + warp;     // 4096 rows
    const float scale = 0.17677669529663687f;
    float v[16];
#pragma unroll
    for (int p = 0; p < 4; p++) {
        size_t off = row * 512 + p * 128 + lane * 4;
        float4 d0 = *reinterpret_cast<const float4*>(&g_dots[off]);
        float4 d1 = *reinterpret_cast<const float4*>(&g_dots[off + DPL]);
        float4 pb = *reinterpret_cast<const float4*>(&g_pbh[off]);
        v[p * 4 + 0] = (d0.x + d1.x) * scale + pb.x;
        v[p * 4 + 1] = (d0.y + d1.y) * scale + pb.y;
        v[p * 4 + 2] = (d0.z + d1.z) * scale + pb.z;
        v[p * 4 + 3] = (d0.w + d1.w) * scale + pb.w;
    }
    float mx = v[0];
#pragma unroll
    for (int i = 1; i < 16; i++) mx = fmaxf(mx, v[i]);
#pragma unroll
    for (int o = 16; o; o >>= 1) mx = fmaxf(mx, __shfl_xor_sync(0xffffffffu, mx, o));
    float s = 0.f;
#pragma unroll
    for (int i = 0; i < 16; i++) { v[i] = expf(v[i] - mx); s += v[i]; }
#pragma unroll
    for (int o = 16; o; o >>= 1) s += __shfl_xor_sync(0xffffffffu, s, o);
    float inv = 1.0f / s;
#pragma unroll
    for (int p = 0; p < 4; p++) {
        size_t off = row * 512 + p * 128 + lane * 4;
        __half2* d = reinterpret_cast<__half2*>(&g_ph[off]);
        d[0] = __floats2half2_rn(v[p * 4 + 0] * inv, v[p * 4 + 1] * inv);
        d[1] = __floats2half2_rn(v[p * 4 + 2] * inv, v[p * 4 + 3] * inv);
    }
}

// ============================================================================
extern "C" void kernel_launch(void* const* d_in, const int* in_sizes, int n_in,
                              void* d_out, int out_size) {
    (void)in_sizes; (void)n_in; (void)out_size;
    const float* x         = (const float*)d_in[0];
    const float* pair_bias = (const float*)d_in[1];
    const float* Wq        = (const float*)d_in[2];
    const float* Wkv       = (const float*)d_in[3];
    const float* Wout      = (const float*)d_in[4];
    const float* b_out     = (const float*)d_in[5];
    const float* ln_g      = (const float*)d_in[6];
    const float* ln_b      = (const float*)d_in[7];
    const float* Wpair     = (const float*)d_in[8];
    const float* Wq_sw     = (const float*)d_in[9];
    const float* bq_sw     = (const float*)d_in[10];
    const float* Wk_sw     = (const float*)d_in[11];
    const float* bk_sw     = (const float*)d_in[12];
    float* out = (float*)d_out;

    static int init_done = 0;
    static cudaStream_t s1;
    static cudaEvent_t e0, e1, e2;
    if (!init_done) {
        cudaFuncSetAttribute(qkv6,       cudaFuncAttributeMaxDynamicSharedMemorySize, SMEM_QKV);
        cudaFuncSetAttribute(g16<1, 32>, cudaFuncAttributeMaxDynamicSharedMemorySize, SMEM_BYTES);
        cudaFuncSetAttribute(g16<2, 8>,  cudaFuncAttributeMaxDynamicSharedMemorySize, SMEM_BYTES);
        cudaFuncSetAttribute(g16<3, 4>,  cudaFuncAttributeMaxDynamicSharedMemorySize, SMEM_BYTES);
        cudaFuncSetAttribute(g16<4, 2>,  cudaFuncAttributeMaxDynamicSharedMemorySize, SMEM_BYTES);
        cudaStreamCreateWithFlags(&s1, cudaStreamNonBlocking);
        cudaEventCreateWithFlags(&e0, cudaEventDisableTiming);
        cudaEventCreateWithFlags(&e1, cudaEventDisableTiming);
        cudaEventCreateWithFlags(&e2, cudaEventDisableTiming);
        init_done = 1;
    }

    // fork: qsw then pbh run on s1 concurrently with the main chain
    cudaEventRecord(e0, 0);
    cudaStreamWaitEvent(s1, e0, 0);
    qsw_kernel<<<NN, 128, 0, s1>>>(x, Wq_sw, bq_sw);
    cudaEventRecord(e2, s1);                                     // qsw done
    pbh_kernel<<<2048, 256, 0, s1>>>(pair_bias, ln_g, ln_b, Wpair);
    cudaEventRecord(e1, s1);                                     // pbh done

    // main chain
    conv_x             <<<8192, 256>>>(x);
    conv_w             <<<576, 256>>>(Wq, Wkv, Wk_sw, Wout);
    cudaStreamWaitEvent(0, e2, 0);                               // ksw needs g_qsw
    g16<4, 2>          <<<dim3(1, 512), 256, SMEM_BYTES>>>(bk_sw, nullptr);
    wrow_softmax_kernel<<<NN * HH / 8, 256>>>();
    qkv6               <<<dim3(1, 512), 256, SMEM_QKV>>>();
    g16<1, 32>         <<<dim3(4, 4, 16), 256, SMEM_BYTES>>>(nullptr, nullptr);

    cudaStreamWaitEvent(0, e1, 0);                               // attn needs g_pbh
    attn_softmax_kernel<<<NN * HH / 8, 256>>>();
    g16<2, 8>          <<<dim3(32, 4, 8), 256, SMEM_BYTES>>>(nullptr, nullptr);
    g16<3, 4>          <<<dim3(1, 512), 256, SMEM_BYTES>>>(b_out, out);
}